// round 10
// baseline (speedup 1.0000x reference)
#include <cuda_runtime.h>
#include <cuda_fp16.h>
#include <cstdint>

// out[M,256] = X[M,256] * tril(W)^T + b  via single fp16 mma.sync.
// CTA tile 256x64, 8 warps, warp tile 32x64 -> X rows are WARP-PRIVATE.
// Each warp double-buffers its own X chunk in private smem; the mainloop has
// NO block-wide barriers (only __syncwarp). W preloaded to shared smem once.
// Triangular K-skip per N-block. 2 CTAs/SM.

#define TDIM 256
#define BM   256
#define BN   64
#define NTHREADS 256

// smem: W[64][512B] swizzled | per-warp X buffers (8 x 4KB: 2 stages x 2KB)
#define OW    0
#define OXB   32768
#define SM_TOTAL 65536

__device__ __half g_Wh[TDIM * TDIM];

__global__ void prep_w(const float* __restrict__ W) {
    int n = blockIdx.x, k = threadIdx.x;
    float v = (k <= n) ? W[n * TDIM + k] : 0.0f;
    g_Wh[n * TDIM + k] = __float2half_rn(v);
}

__device__ __forceinline__ uint32_t smem_u32(const void* p) {
    uint32_t a;
    asm("{ .reg .u64 t; cvta.to.shared.u64 t, %1; cvt.u32.u64 %0, t; }" : "=r"(a) : "l"(p));
    return a;
}
// W layout: row n = 512B (256 fp16 K-cols), 16B chunk c swizzled by n&7
__device__ __forceinline__ uint32_t woff(int n, int c) {
    return (uint32_t)(n * 512 + ((c ^ (n & 7)) << 4));
}
// warp-private X fp16 layout (32 rows x 32 cols per stage = 2KB):
// two 64B rows per 128B smem row; 16B chunkin 0..7 swizzled by (row>>1)&7
__device__ __forceinline__ uint32_t xoff(int row, int chunkin) {
    return (uint32_t)((row >> 1) * 128 + ((chunkin ^ ((row >> 1) & 7)) << 4));
}
// STS address: local row 0..31, fq = float4 index 0..7 within the 32-float row
__device__ __forceinline__ uint32_t xsts(int row, int fq) {
    int chunkin = ((row & 1) << 2) | (fq >> 1);
    return xoff(row, chunkin) + (uint32_t)((fq & 1) * 8);
}

#define CP16(dst, src) \
    asm volatile("cp.async.cg.shared.global [%0], [%1], 16;" :: "r"(dst), "l"(src) : "memory")
#define CP_COMMIT() asm volatile("cp.async.commit_group;" ::: "memory")
#define CP_WAIT0()  asm volatile("cp.async.wait_group 0;" ::: "memory")

__device__ __forceinline__ void ldsm4(uint32_t (&r)[4], uint32_t a) {
    asm volatile("ldmatrix.sync.aligned.m8n8.x4.shared.b16 {%0,%1,%2,%3}, [%4];"
        : "=r"(r[0]), "=r"(r[1]), "=r"(r[2]), "=r"(r[3]) : "r"(a));
}
__device__ __forceinline__ void mma16816(float (&d)[4], const uint32_t (&a)[4],
                                         const uint32_t* b) {
    asm volatile("mma.sync.aligned.m16n8k16.row.col.f32.f16.f16.f32 "
        "{%0,%1,%2,%3}, {%4,%5,%6,%7}, {%8,%9}, {%0,%1,%2,%3};"
        : "+f"(d[0]), "+f"(d[1]), "+f"(d[2]), "+f"(d[3])
        : "r"(a[0]), "r"(a[1]), "r"(a[2]), "r"(a[3]), "r"(b[0]), "r"(b[1]));
}
__device__ __forceinline__ uint32_t pack2f(float lo, float hi) {
    uint32_t r;
    asm("cvt.rn.f16x2.f32 %0, %1, %2;" : "=r"(r) : "f"(hi), "f"(lo));
    return r;
}
__device__ __forceinline__ void xstore(char* buf, int row, int fq, float4 v) {
    uint2 h = make_uint2(pack2f(v.x, v.y), pack2f(v.z, v.w));
    *reinterpret_cast<uint2*>(buf + xsts(row, fq)) = h;
}

__global__ __launch_bounds__(NTHREADS, 2)
void triu_v10(const float* __restrict__ X, const float* __restrict__ bias,
              float* __restrict__ out)
{
    extern __shared__ char smem[];
    const uint32_t sb = smem_u32(smem);
    const int tid = threadIdx.x;
    const int wid = tid >> 5, lane = tid & 31;

    const int bid = blockIdx.x;
    const int nb = bid & 3;                            // n-block 0..3
    const size_t m0 = (size_t)(bid >> 2) * BM;
    const int n0 = nb * BN;
    const int nch = 2 * (nb + 1);                      // CK=32 chunks: 2,4,6,8

    // ---- prologue: preload needed W via cp.async, ONE block barrier ----
    const int wchunks = 8 * (nb + 1);                  // 16B chunks per row (<=32)
    #pragma unroll
    for (int i = 0; i < 8; i++) {
        int s = tid + i * NTHREADS;                    // 0..2047
        int n = s >> 5, c = s & 31;
        if (c < wchunks)
            CP16(sb + OW + woff(n, c), &g_Wh[(n0 + n) * TDIM + c * 8]);
    }
    CP_COMMIT();

    // warp-private pointers
    char* xbuf = smem + OXB + wid * 4096;              // 2 stages x 2KB
    const size_t wr0 = m0 + wid * 32;                  // this warp's 32 X rows
    const int lrow = lane >> 3, lfq = lane & 7;        // 4 rows x 8 lanes per pass

    // ---- stage X chunk 0 into stage 0 ----
    #pragma unroll
    for (int p = 0; p < 8; p++) {
        int row = p * 4 + lrow;
        float4 v = *reinterpret_cast<const float4*>(&X[(wr0 + row) * TDIM + lfq * 4]);
        xstore(xbuf, row, lfq, v);
    }
    CP_WAIT0();
    __syncthreads();                                   // W visible to all warps

    float acc[2][8][4];
    #pragma unroll
    for (int i = 0; i < 2; i++)
        #pragma unroll
        for (int j = 0; j < 8; j++)
            #pragma unroll
            for (int e = 0; e < 4; e++) acc[i][j][e] = 0.0f;

    const int g = lane >> 3;
    float4 xv[4];                                      // prefetch: passes 0..3
    int st = 0;
    for (int c = 0; c < nch; c++) {
        const bool more = (c + 1 < nch);
        const int k0n = (c + 1) * 32;
        if (more) {
            #pragma unroll
            for (int p = 0; p < 4; p++) {
                int row = p * 4 + lrow;
                xv[p] = *reinterpret_cast<const float4*>(&X[(wr0 + row) * TDIM + k0n + lfq * 4]);
            }
        }

        char* cur = xbuf + (st ? 2048 : 0);
        const uint32_t curb = sb + (uint32_t)(cur - smem);
        #pragma unroll
        for (int kk = 0; kk < 2; kk++) {
            const int kg = c * 2 + kk;                 // global k16 index
            uint32_t ah[2][4], bh[8][2];
            #pragma unroll
            for (int i = 0; i < 2; i++) {
                int ar = i * 16 + (lane & 15);
                int chunkin = ((ar & 1) << 2) | (2 * kk + (lane >> 4));
                ldsm4(ah[i], curb + xoff(ar, chunkin));
            }
            #pragma unroll
            for (int j2 = 0; j2 < 4; j2++) {
                int br = j2 * 16 + ((g >> 1) << 3) + (lane & 7);
                int wc = 2 * kg + (g & 1);
                uint32_t r[4];
                ldsm4(r, sb + OW + woff(br, wc));
                bh[2 * j2][0] = r[0]; bh[2 * j2][1] = r[1];
                bh[2 * j2 + 1][0] = r[2]; bh[2 * j2 + 1][1] = r[3];
            }
            #pragma unroll
            for (int i = 0; i < 2; i++)
                #pragma unroll
                for (int j = 0; j < 8; j++)
                    mma16816(acc[i][j], ah[i], bh[j]);
        }

        if (more) {
            char* nbuf = xbuf + (st ? 0 : 2048);
            #pragma unroll
            for (int p = 0; p < 4; p++)                // prefetched passes
                xstore(nbuf, p * 4 + lrow, lfq, xv[p]);
            #pragma unroll
            for (int p = 4; p < 8; p++) {              // late passes
                int row = p * 4 + lrow;
                float4 v = *reinterpret_cast<const float4*>(&X[(wr0 + row) * TDIM + k0n + lfq * 4]);
                xstore(nbuf, row, lfq, v);
            }
        }
        __syncwarp();
        st ^= 1;
    }

    // ---- epilogue: warp-private smem bounce -> coalesced STG.128 ----
    // reuse this warp's own 4KB X buffer (in-warp order makes it safe)
    __syncwarp();
    const int ncb = n0 + 2 * (lane & 3);
    float2 bj[8];
    #pragma unroll
    for (int j = 0; j < 8; j++)
        bj[j] = *reinterpret_cast<const float2*>(&bias[ncb + j * 8]);

    #pragma unroll
    for (int h = 0; h < 2; h++) {                      // column halves (32 cols)
        #pragma unroll
        for (int i = 0; i < 2; i++) {
            #pragma unroll
            for (int jj = 0; jj < 4; jj++) {
                const int j = 4 * h + jj;
                int chunk = 2 * jj + ((lane & 3) >> 1);
                int off = (lane & 1) * 8;
                int rl0 = i * 16 + (lane >> 2), rl1 = rl0 + 8;
                float2 v0 = make_float2(acc[i][j][0] + bj[j].x, acc[i][j][1] + bj[j].y);
                float2 v1 = make_float2(acc[i][j][2] + bj[j].x, acc[i][j][3] + bj[j].y);
                *reinterpret_cast<float2*>(xbuf + rl0 * 128 + ((chunk ^ (rl0 & 7)) << 4) + off) = v0;
                *reinterpret_cast<float2*>(xbuf + rl1 * 128 + ((chunk ^ (rl1 & 7)) << 4) + off) = v1;
            }
        }
        __syncwarp();
        #pragma unroll
        for (int it = 0; it < 8; it++) {
            int rl = it * 4 + (lane >> 3);
            int ch = (lane & 7) ^ (rl & 7);
            float4 v = *reinterpret_cast<const float4*>(xbuf + rl * 128 + (ch << 4));
            *reinterpret_cast<float4*>(&out[(wr0 + rl) * TDIM + n0 + h * 32 + (lane & 7) * 4]) = v;
        }
        __syncwarp();
    }
}

extern "C" void kernel_launch(void* const* d_in, const int* in_sizes, int n_in,
                              void* d_out, int out_size)
{
    const float* x = (const float*)d_in[0];
    const float* W = (const float*)d_in[1];
    const float* b = (const float*)d_in[2];
    float* out = (float*)d_out;

    prep_w<<<TDIM, TDIM>>>(W);

    cudaFuncSetAttribute(triu_v10, cudaFuncAttributeMaxDynamicSharedMemorySize, SM_TOTAL);
    const int M = in_sizes[0] / TDIM;                  // 262144
    const int nblocks = (M / BM) * (TDIM / BN);        // 4096
    triu_v10<<<nblocks, NTHREADS, SM_TOTAL>>>(x, b, out);
}